// round 1
// baseline (speedup 1.0000x reference)
#include <cuda_runtime.h>

#define NN 100000
#define FD 128
#define RR 4
#define EE 1600000

// Scratch (device globals: no allocation allowed in kernel_launch)
__device__ float g_S[(size_t)NN * RR * FD];     // 204.8 MB segment sums
__device__ float g_xbuf[(size_t)NN * FD];       // 51.2 MB layer-1 activations
__device__ int   g_cnt[NN * RR];
__device__ float g_inv[NN * RR];
__device__ int   g_is64;

// ---------------------------------------------------------------------------
// Detect whether edge_index/edge_type arrived as int64 or int32.
// (JAX downcasts jnp.int64 -> int32 unless x64 is enabled; handle both.)
// If data is int32, reading as int64 packs two values -> huge numbers.
__global__ void detect_kernel(const void* ei) {
    const long long* p = (const long long*)ei;
    int lane = threadIdx.x;
    int bad = 0;
    for (int i = lane; i < 256; i += 32) {
        long long v = p[i];
        if (v < 0 || v >= NN) bad = 1;
    }
    unsigned m = __ballot_sync(0xffffffffu, bad);
    if (lane == 0) g_is64 = (m == 0) ? 1 : 0;
}

__device__ __forceinline__ int ld_idx(const void* p, size_t i, int is64) {
    return is64 ? (int)((const long long*)p)[i] : ((const int*)p)[i];
}

__global__ void zero_cnt_kernel() {
    int i = blockIdx.x * blockDim.x + threadIdx.x;
    if (i < NN * RR) g_cnt[i] = 0;
}

__global__ void count_kernel(const void* ei, const void* et) {
    int is64 = g_is64;
    int stride = gridDim.x * blockDim.x;
    for (int e = blockIdx.x * blockDim.x + threadIdx.x; e < EE; e += stride) {
        int dst = ld_idx(ei, (size_t)EE + e, is64);
        int r   = ld_idx(et, (size_t)e, is64);
        atomicAdd(&g_cnt[dst * RR + r], 1);
    }
}

__global__ void inv_kernel() {
    int i = blockIdx.x * blockDim.x + threadIdx.x;
    if (i < NN * RR) {
        int c = g_cnt[i];
        g_inv[i] = 1.0f / (float)(c > 0 ? c : 1);
    }
}

__global__ void zero_S_kernel() {
    size_t n4 = (size_t)NN * RR * FD / 4;
    float4 z = make_float4(0.f, 0.f, 0.f, 0.f);
    size_t stride = (size_t)gridDim.x * blockDim.x;
    for (size_t i = (size_t)blockIdx.x * blockDim.x + threadIdx.x; i < n4; i += stride)
        ((float4*)g_S)[i] = z;
}

// One warp per edge: read x[src] (512B coalesced, x fits in L2), vector-atomic
// into S[dst*R + r]. 16B red.global keeps instruction count at 1/lane/edge.
__global__ void scatter_kernel(const float* xin, int use_internal,
                               const void* ei, const void* et) {
    const float* xp = use_internal ? g_xbuf : xin;
    int is64 = g_is64;
    int gw = (blockIdx.x * blockDim.x + threadIdx.x) >> 5;
    int lane = threadIdx.x & 31;
    int nw = (gridDim.x * blockDim.x) >> 5;
    for (int e = gw; e < EE; e += nw) {
        int src = ld_idx(ei, (size_t)e, is64);
        int dst = ld_idx(ei, (size_t)EE + e, is64);
        int r   = ld_idx(et, (size_t)e, is64);
        float4 v = ((const float4*)(xp + (size_t)src * FD))[lane];
        float* sp = g_S + ((size_t)dst * RR + r) * FD + lane * 4;
        asm volatile("red.global.add.v4.f32 [%0], {%1,%2,%3,%4};"
                     :: "l"(sp), "f"(v.x), "f"(v.y), "f"(v.z), "f"(v.w)
                     : "memory");
    }
}

// Fused GEMM: out[n,:] = relu( [S[n]*inv | x[n]] (1x640) @ [W;root] (640x128) + bias )
// 128x128 block tile, 256 threads, 8x8 microtile, BK=8, register prefetch.
// inv-count scaling applied inline on the A load (each A element read once).
__global__ __launch_bounds__(256, 2)
void gemm_kernel(const float* xin, int use_internal_in,
                 const float* __restrict__ Wl,     // [R*FD, FD]
                 const float* __restrict__ rootl,  // [FD, FD]
                 const float* __restrict__ biasl,  // [FD]
                 float* outp, int use_internal_out) {
    const float* xp = use_internal_in ? g_xbuf : xin;
    float* op = use_internal_out ? g_xbuf : outp;

    __shared__ float As[8][128];
    __shared__ float Bs[8][128];

    const int tid = threadIdx.x;
    const int m0 = blockIdx.x * 128;
    const int tx = tid & 15;
    const int ty = tid >> 4;

    const int arow = m0 + (tid >> 1);
    const int ak = (tid & 1) * 4;
    const bool av = arow < NN;
    const float* Srow = g_S + (size_t)arow * (RR * FD);
    const float* Xrow = xp + (size_t)arow * FD;

    const int bk = tid >> 5;         // 0..7
    const int bc = (tid & 31) * 4;   // 0..124

    float acc[8][8];
#pragma unroll
    for (int i = 0; i < 8; i++)
#pragma unroll
        for (int j = 0; j < 8; j++) acc[i][j] = 0.f;

    const int KS = RR * FD;          // 512
    const int K = KS + FD;           // 640

    float4 aReg = make_float4(0.f, 0.f, 0.f, 0.f);
    float4 bReg;
    {
        if (av) {
            aReg = *(const float4*)(Srow + ak);
            float s = g_inv[arow * RR + (ak >> 7)];
            aReg.x *= s; aReg.y *= s; aReg.z *= s; aReg.w *= s;
        }
        bReg = *(const float4*)(Wl + (size_t)bk * FD + bc);
    }

    for (int kt = 0; kt < K; kt += 8) {
        As[ak + 0][tid >> 1] = aReg.x;
        As[ak + 1][tid >> 1] = aReg.y;
        As[ak + 2][tid >> 1] = aReg.z;
        As[ak + 3][tid >> 1] = aReg.w;
        *(float4*)&Bs[bk][bc] = bReg;
        __syncthreads();

        int kn = kt + 8;
        if (kn < K) {
            if (av) {
                int k = kn + ak;
                if (k < KS) {
                    aReg = *(const float4*)(Srow + k);
                    float s = g_inv[arow * RR + (k >> 7)];
                    aReg.x *= s; aReg.y *= s; aReg.z *= s; aReg.w *= s;
                } else {
                    aReg = *(const float4*)(Xrow + (k - KS));
                }
            }
            int kb = kn + bk;
            const float* bp = (kb < KS) ? (Wl + (size_t)kb * FD + bc)
                                        : (rootl + (size_t)(kb - KS) * FD + bc);
            bReg = *(const float4*)bp;
        }

#pragma unroll
        for (int k = 0; k < 8; k++) {
            float a[8], b[8];
            *(float4*)&a[0] = *(const float4*)&As[k][ty * 8];
            *(float4*)&a[4] = *(const float4*)&As[k][ty * 8 + 4];
            *(float4*)&b[0] = *(const float4*)&Bs[k][tx * 8];
            *(float4*)&b[4] = *(const float4*)&Bs[k][tx * 8 + 4];
#pragma unroll
            for (int i = 0; i < 8; i++)
#pragma unroll
                for (int j = 0; j < 8; j++)
                    acc[i][j] += a[i] * b[j];
        }
        __syncthreads();
    }

    float bb[8];
    *(float4*)&bb[0] = *(const float4*)(biasl + tx * 8);
    *(float4*)&bb[4] = *(const float4*)(biasl + tx * 8 + 4);

#pragma unroll
    for (int i = 0; i < 8; i++) {
        int row = m0 + ty * 8 + i;
        if (row < NN) {
            float4 o0, o1;
            o0.x = fmaxf(acc[i][0] + bb[0], 0.f);
            o0.y = fmaxf(acc[i][1] + bb[1], 0.f);
            o0.z = fmaxf(acc[i][2] + bb[2], 0.f);
            o0.w = fmaxf(acc[i][3] + bb[3], 0.f);
            o1.x = fmaxf(acc[i][4] + bb[4], 0.f);
            o1.y = fmaxf(acc[i][5] + bb[5], 0.f);
            o1.z = fmaxf(acc[i][6] + bb[6], 0.f);
            o1.w = fmaxf(acc[i][7] + bb[7], 0.f);
            *(float4*)(op + (size_t)row * FD + tx * 8) = o0;
            *(float4*)(op + (size_t)row * FD + tx * 8 + 4) = o1;
        }
    }
}

extern "C" void kernel_launch(void* const* d_in, const int* in_sizes, int n_in,
                              void* d_out, int out_size) {
    const float* x      = (const float*)d_in[0];   // [N, F]
    const void*  ei     = d_in[1];                 // [2, E] int64 or int32
    const void*  et     = d_in[2];                 // [E]    int64 or int32
    const float* W      = (const float*)d_in[3];   // [L, R, F, F]
    const float* roots  = (const float*)d_in[4];   // [L, F, F]
    const float* biases = (const float*)d_in[5];   // [L, F]
    float* out = (float*)d_out;                    // [N, F]

    detect_kernel<<<1, 32>>>(ei);
    zero_cnt_kernel<<<(NN * RR + 255) / 256, 256>>>();
    count_kernel<<<2048, 256>>>(ei, et);
    inv_kernel<<<(NN * RR + 255) / 256, 256>>>();

    const int gemm_blocks = (NN + 127) / 128;
    for (int l = 0; l < 2; l++) {
        zero_S_kernel<<<8192, 256>>>();
        scatter_kernel<<<4096, 256>>>(x, l, ei, et);
        gemm_kernel<<<gemm_blocks, 256>>>(
            x, l,
            W + (size_t)l * RR * FD * FD,
            roots + (size_t)l * FD * FD,
            biases + (size_t)l * FD,
            out, (l == 0) ? 1 : 0);
    }
}

// round 2
// speedup vs baseline: 1.0038x; 1.0038x over previous
#include <cuda_runtime.h>

#define NN 100000
#define FD 128
#define RR 4
#define EE 1600000

// Scratch (device globals: no allocation allowed in kernel_launch)
__device__ float g_S[(size_t)NN * RR * FD];     // 204.8 MB segment sums
__device__ float g_xbuf[(size_t)NN * FD];       // 51.2 MB layer-1 activations
__device__ int   g_cnt[NN * RR];
__device__ float g_inv[NN * RR];
__device__ int   g_is64;

// ---------------------------------------------------------------------------
// Detect whether edge_index/edge_type arrived as int64 or int32.
// (JAX downcasts jnp.int64 -> int32 unless x64 is enabled; handle both.)
// If data is int32, reading as int64 packs two values -> huge numbers.
__global__ void detect_kernel(const void* ei) {
    const long long* p = (const long long*)ei;
    int lane = threadIdx.x;
    int bad = 0;
    for (int i = lane; i < 256; i += 32) {
        long long v = p[i];
        if (v < 0 || v >= NN) bad = 1;
    }
    unsigned m = __ballot_sync(0xffffffffu, bad);
    if (lane == 0) g_is64 = (m == 0) ? 1 : 0;
}

__device__ __forceinline__ int ld_idx(const void* p, size_t i, int is64) {
    return is64 ? (int)((const long long*)p)[i] : ((const int*)p)[i];
}

__global__ void zero_cnt_kernel() {
    int i = blockIdx.x * blockDim.x + threadIdx.x;
    if (i < NN * RR) g_cnt[i] = 0;
}

__global__ void count_kernel(const void* ei, const void* et) {
    int is64 = g_is64;
    int stride = gridDim.x * blockDim.x;
    for (int e = blockIdx.x * blockDim.x + threadIdx.x; e < EE; e += stride) {
        int dst = ld_idx(ei, (size_t)EE + e, is64);
        int r   = ld_idx(et, (size_t)e, is64);
        atomicAdd(&g_cnt[dst * RR + r], 1);
    }
}

__global__ void inv_kernel() {
    int i = blockIdx.x * blockDim.x + threadIdx.x;
    if (i < NN * RR) {
        int c = g_cnt[i];
        g_inv[i] = 1.0f / (float)(c > 0 ? c : 1);
    }
}

__global__ void zero_S_kernel() {
    size_t n4 = (size_t)NN * RR * FD / 4;
    float4 z = make_float4(0.f, 0.f, 0.f, 0.f);
    size_t stride = (size_t)gridDim.x * blockDim.x;
    for (size_t i = (size_t)blockIdx.x * blockDim.x + threadIdx.x; i < n4; i += stride)
        ((float4*)g_S)[i] = z;
}

// One warp per edge: read x[src] (512B coalesced, x fits in L2), vector-atomic
// into S[dst*R + r]. 16B red.global keeps instruction count at 1/lane/edge.
__global__ void scatter_kernel(const float* xin, int use_internal,
                               const void* ei, const void* et) {
    const float* xp = use_internal ? g_xbuf : xin;
    int is64 = g_is64;
    int gw = (blockIdx.x * blockDim.x + threadIdx.x) >> 5;
    int lane = threadIdx.x & 31;
    int nw = (gridDim.x * blockDim.x) >> 5;
    for (int e = gw; e < EE; e += nw) {
        int src = ld_idx(ei, (size_t)e, is64);
        int dst = ld_idx(ei, (size_t)EE + e, is64);
        int r   = ld_idx(et, (size_t)e, is64);
        float4 v = ((const float4*)(xp + (size_t)src * FD))[lane];
        float* sp = g_S + ((size_t)dst * RR + r) * FD + lane * 4;
        asm volatile("red.global.add.v4.f32 [%0], {%1,%2,%3,%4};"
                     :: "l"(sp), "f"(v.x), "f"(v.y), "f"(v.z), "f"(v.w)
                     : "memory");
    }
}

// Fused GEMM: out[n,:] = relu( [S[n]*inv | x[n]] (1x640) @ [W;root] (640x128) + bias )
// 128x128 block tile, 256 threads, 8x8 microtile, BK=8, register prefetch.
// inv-count scaling applied inline on the A load (each A element read once).
__global__ __launch_bounds__(256, 2)
void gemm_kernel(const float* xin, int use_internal_in,
                 const float* __restrict__ Wl,     // [R*FD, FD]
                 const float* __restrict__ rootl,  // [FD, FD]
                 const float* __restrict__ biasl,  // [FD]
                 float* outp, int use_internal_out) {
    const float* xp = use_internal_in ? g_xbuf : xin;
    float* op = use_internal_out ? g_xbuf : outp;

    __shared__ float As[8][128];
    __shared__ float Bs[8][128];

    const int tid = threadIdx.x;
    const int m0 = blockIdx.x * 128;
    const int tx = tid & 15;
    const int ty = tid >> 4;

    const int arow = m0 + (tid >> 1);
    const int ak = (tid & 1) * 4;
    const bool av = arow < NN;
    const float* Srow = g_S + (size_t)arow * (RR * FD);
    const float* Xrow = xp + (size_t)arow * FD;

    const int bk = tid >> 5;         // 0..7
    const int bc = (tid & 31) * 4;   // 0..124

    float acc[8][8];
#pragma unroll
    for (int i = 0; i < 8; i++)
#pragma unroll
        for (int j = 0; j < 8; j++) acc[i][j] = 0.f;

    const int KS = RR * FD;          // 512
    const int K = KS + FD;           // 640

    float4 aReg = make_float4(0.f, 0.f, 0.f, 0.f);
    float4 bReg;
    {
        if (av) {
            aReg = *(const float4*)(Srow + ak);
            float s = g_inv[arow * RR + (ak >> 7)];
            aReg.x *= s; aReg.y *= s; aReg.z *= s; aReg.w *= s;
        }
        bReg = *(const float4*)(Wl + (size_t)bk * FD + bc);
    }

    for (int kt = 0; kt < K; kt += 8) {
        As[ak + 0][tid >> 1] = aReg.x;
        As[ak + 1][tid >> 1] = aReg.y;
        As[ak + 2][tid >> 1] = aReg.z;
        As[ak + 3][tid >> 1] = aReg.w;
        *(float4*)&Bs[bk][bc] = bReg;
        __syncthreads();

        int kn = kt + 8;
        if (kn < K) {
            if (av) {
                int k = kn + ak;
                if (k < KS) {
                    aReg = *(const float4*)(Srow + k);
                    float s = g_inv[arow * RR + (k >> 7)];
                    aReg.x *= s; aReg.y *= s; aReg.z *= s; aReg.w *= s;
                } else {
                    aReg = *(const float4*)(Xrow + (k - KS));
                }
            }
            int kb = kn + bk;
            const float* bp = (kb < KS) ? (Wl + (size_t)kb * FD + bc)
                                        : (rootl + (size_t)(kb - KS) * FD + bc);
            bReg = *(const float4*)bp;
        }

#pragma unroll
        for (int k = 0; k < 8; k++) {
            float a[8], b[8];
            *(float4*)&a[0] = *(const float4*)&As[k][ty * 8];
            *(float4*)&a[4] = *(const float4*)&As[k][ty * 8 + 4];
            *(float4*)&b[0] = *(const float4*)&Bs[k][tx * 8];
            *(float4*)&b[4] = *(const float4*)&Bs[k][tx * 8 + 4];
#pragma unroll
            for (int i = 0; i < 8; i++)
#pragma unroll
                for (int j = 0; j < 8; j++)
                    acc[i][j] += a[i] * b[j];
        }
        __syncthreads();
    }

    float bb[8];
    *(float4*)&bb[0] = *(const float4*)(biasl + tx * 8);
    *(float4*)&bb[4] = *(const float4*)(biasl + tx * 8 + 4);

#pragma unroll
    for (int i = 0; i < 8; i++) {
        int row = m0 + ty * 8 + i;
        if (row < NN) {
            float4 o0, o1;
            o0.x = fmaxf(acc[i][0] + bb[0], 0.f);
            o0.y = fmaxf(acc[i][1] + bb[1], 0.f);
            o0.z = fmaxf(acc[i][2] + bb[2], 0.f);
            o0.w = fmaxf(acc[i][3] + bb[3], 0.f);
            o1.x = fmaxf(acc[i][4] + bb[4], 0.f);
            o1.y = fmaxf(acc[i][5] + bb[5], 0.f);
            o1.z = fmaxf(acc[i][6] + bb[6], 0.f);
            o1.w = fmaxf(acc[i][7] + bb[7], 0.f);
            *(float4*)(op + (size_t)row * FD + tx * 8) = o0;
            *(float4*)(op + (size_t)row * FD + tx * 8 + 4) = o1;
        }
    }
}

extern "C" void kernel_launch(void* const* d_in, const int* in_sizes, int n_in,
                              void* d_out, int out_size) {
    const float* x      = (const float*)d_in[0];   // [N, F]
    const void*  ei     = d_in[1];                 // [2, E] int64 or int32
    const void*  et     = d_in[2];                 // [E]    int64 or int32
    const float* W      = (const float*)d_in[3];   // [L, R, F, F]
    const float* roots  = (const float*)d_in[4];   // [L, F, F]
    const float* biases = (const float*)d_in[5];   // [L, F]
    float* out = (float*)d_out;                    // [N, F]

    detect_kernel<<<1, 32>>>(ei);
    zero_cnt_kernel<<<(NN * RR + 255) / 256, 256>>>();
    count_kernel<<<2048, 256>>>(ei, et);
    inv_kernel<<<(NN * RR + 255) / 256, 256>>>();

    const int gemm_blocks = (NN + 127) / 128;
    for (int l = 0; l < 2; l++) {
        zero_S_kernel<<<8192, 256>>>();
        scatter_kernel<<<4096, 256>>>(x, l, ei, et);
        gemm_kernel<<<gemm_blocks, 256>>>(
            x, l,
            W + (size_t)l * RR * FD * FD,
            roots + (size_t)l * FD * FD,
            biases + (size_t)l * FD,
            out, (l == 0) ? 1 : 0);
    }
}

// round 5
// speedup vs baseline: 1.2752x; 1.2704x over previous
#include <cuda_runtime.h>
#include <cuda_bf16.h>
#include <cstdint>

#define NN 100000
#define FD 128
#define RR 4
#define EE 1600000

// Scratch (device globals: no allocation allowed in kernel_launch)
__device__ float g_S[(size_t)NN * RR * FD];     // 204.8 MB segment sums
__device__ float g_xbuf[(size_t)NN * FD];       // 51.2 MB layer-1 activations
__device__ int   g_cnt[NN * RR];
__device__ float g_inv[NN * RR];
__device__ int   g_is64;
// Pre-split B^T = [W;root]^T as bf16 hi/lo, layout [L][n=128][k=640]
__device__ __nv_bfloat16 g_Bth[2 * 128 * 640];
__device__ __nv_bfloat16 g_Btl[2 * 128 * 640];

// ---------------------------------------------------------------------------
__global__ void detect_kernel(const void* ei) {
    const long long* p = (const long long*)ei;
    int lane = threadIdx.x;
    int bad = 0;
    for (int i = lane; i < 256; i += 32) {
        long long v = p[i];
        if (v < 0 || v >= NN) bad = 1;
    }
    unsigned m = __ballot_sync(0xffffffffu, bad);
    if (lane == 0) g_is64 = (m == 0) ? 1 : 0;
}

__device__ __forceinline__ int ld_idx(const void* p, size_t i, int is64) {
    return is64 ? (int)((const long long*)p)[i] : ((const int*)p)[i];
}

__global__ void zero_cnt_kernel() {
    int i = blockIdx.x * blockDim.x + threadIdx.x;
    if (i < NN * RR) g_cnt[i] = 0;
}

__global__ void count_kernel(const void* ei, const void* et) {
    int is64 = g_is64;
    int stride = gridDim.x * blockDim.x;
    for (int e = blockIdx.x * blockDim.x + threadIdx.x; e < EE; e += stride) {
        int dst = ld_idx(ei, (size_t)EE + e, is64);
        int r   = ld_idx(et, (size_t)e, is64);
        atomicAdd(&g_cnt[dst * RR + r], 1);
    }
}

__global__ void inv_kernel() {
    int i = blockIdx.x * blockDim.x + threadIdx.x;
    if (i < NN * RR) {
        int c = g_cnt[i];
        g_inv[i] = 1.0f / (float)(c > 0 ? c : 1);
    }
}

__global__ void zero_S_kernel() {
    size_t n4 = (size_t)NN * RR * FD / 4;
    float4 z = make_float4(0.f, 0.f, 0.f, 0.f);
    size_t stride = (size_t)gridDim.x * blockDim.x;
    for (size_t i = (size_t)blockIdx.x * blockDim.x + threadIdx.x; i < n4; i += stride)
        ((float4*)g_S)[i] = z;
}

__global__ void scatter_kernel(const float* xin, int use_internal,
                               const void* ei, const void* et) {
    const float* xp = use_internal ? g_xbuf : xin;
    int is64 = g_is64;
    int gw = (blockIdx.x * blockDim.x + threadIdx.x) >> 5;
    int lane = threadIdx.x & 31;
    int nw = (gridDim.x * blockDim.x) >> 5;
    for (int e = gw; e < EE; e += nw) {
        int src = ld_idx(ei, (size_t)e, is64);
        int dst = ld_idx(ei, (size_t)EE + e, is64);
        int r   = ld_idx(et, (size_t)e, is64);
        float4 v = ((const float4*)(xp + (size_t)src * FD))[lane];
        float* sp = g_S + ((size_t)dst * RR + r) * FD + lane * 4;
        asm volatile("red.global.add.v4.f32 [%0], {%1,%2,%3,%4};"
                     :: "l"(sp), "f"(v.x), "f"(v.y), "f"(v.z), "f"(v.w)
                     : "memory");
    }
}

// ---------------------------------------------------------------------------
// Prep: B^T[n][k] = (k<512 ? W[l][k][n] : root[l][k-512][n]) split into bf16 hi/lo
__global__ void prep_b_kernel(const float* __restrict__ W,
                              const float* __restrict__ roots) {
    int idx = blockIdx.x * blockDim.x + threadIdx.x;
    if (idx >= 2 * 128 * 640) return;
    int l = idx / (128 * 640);
    int rem = idx % (128 * 640);
    int n = rem / 640;
    int k = rem % 640;
    float v = (k < 512) ? W[(size_t)l * 65536 + (size_t)k * 128 + n]
                        : roots[(size_t)l * 16384 + (size_t)(k - 512) * 128 + n];
    __nv_bfloat16 h = __float2bfloat16(v);
    float hf = __bfloat162float(h);
    __nv_bfloat16 lo = __float2bfloat16(v - hf);
    g_Bth[idx] = h;
    g_Btl[idx] = lo;
}

// ---------------------------------------------------------------------------
__device__ __forceinline__ uint32_t s2u(const void* p) {
    uint32_t a;
    asm("{ .reg .u64 t; cvta.to.shared.u64 t, %1; cvt.u32.u64 %0, t; }"
        : "=r"(a) : "l"(p));
    return a;
}

__device__ __forceinline__ void split_pair(float x, float y,
                                           uint32_t& h, uint32_t& l) {
    __nv_bfloat162 hb = __float22bfloat162_rn(make_float2(x, y));
    float2 hf = __bfloat1622float2(hb);
    __nv_bfloat162 lb = __float22bfloat162_rn(make_float2(x - hf.x, y - hf.y));
    h = *reinterpret_cast<uint32_t*>(&hb);
    l = *reinterpret_cast<uint32_t*>(&lb);
}

__device__ __forceinline__ void cpa16(uint32_t d, const void* s) {
    asm volatile("cp.async.cg.shared.global [%0], [%1], 16;"
                 :: "r"(d), "l"(s) : "memory");
}

#define MMA16816(C, A, B) \
    asm volatile("mma.sync.aligned.m16n8k16.row.col.f32.bf16.bf16.f32 " \
        "{%0,%1,%2,%3}, {%4,%5,%6,%7}, {%8,%9}, {%0,%1,%2,%3};" \
        : "+f"((C)[0]), "+f"((C)[1]), "+f"((C)[2]), "+f"((C)[3]) \
        : "r"((A)[0]), "r"((A)[1]), "r"((A)[2]), "r"((A)[3]), \
          "r"((B)[0]), "r"((B)[1]))

// SMEM layout per stage: sAh[128][72] | sAl | sBh[128][72] | sBl  (bf16, 18432B each)
#define TB   18432
#define STG  (4 * TB)          // 73728 per stage
#define SM_TOTAL (2 * STG + 512)

// ---------------------------------------------------------------------------
// Fused tensor GEMM via mma.sync (HMMA):
//   out = relu([S*inv | x] (Nx640) @ Bt^T (640x128) + bias)
// bf16x3 split (Ah*Bh + Al*Bh + Ah*Bl). CTA tile 128x128, 8 warps (4x2),
// warp tile 32x64, K chunks of 64, double-buffered, cp.async for B.
__global__ __launch_bounds__(256, 1)
void gemm_mma_kernel(const float* xin, int use_internal_in, int layer,
                     const float* __restrict__ biasl,
                     float* outp, int use_internal_out) {
    extern __shared__ char smem[];
    const uint32_t sb = s2u(smem);
    const int tid = threadIdx.x;
    const int wid = tid >> 5, lane = tid & 31;
    const int g = lane >> 2, tq = lane & 3;
    const int wm = wid >> 1, wn = wid & 1;

    const float* xp = use_internal_in ? g_xbuf : xin;
    float* op = use_internal_out ? g_xbuf : outp;
    const int m0 = blockIdx.x * 128;

    float* sbias = (float*)(smem + 2 * STG);
    if (tid < 128) sbias[tid] = biasl[tid];

    // A loader: thread -> (row, half-of-64)
    const int arow = tid >> 1;
    const int ahalf = tid & 1;
    const int rg = m0 + arow;
    const bool rv = rg < NN;

    // B loader: thread -> (n, half)
    const int bn = tid & 127;
    const int bhf = tid >> 7;
    const char* gBh = (const char*)(g_Bth + (size_t)(layer * 128 + bn) * 640);
    const char* gBl = (const char*)(g_Btl + (size_t)(layer * 128 + bn) * 640);

    float4 aPref[8];

    auto ldA = [&](int c) {
        const float* src;
        float s = 1.f;
        if (c < 8) {
            src = g_S + (size_t)rg * 512 + c * 64 + ahalf * 32;
            if (rv) s = g_inv[rg * 4 + (c >> 1)];
        } else {
            src = xp + (size_t)rg * 128 + (c - 8) * 64 + ahalf * 32;
        }
#pragma unroll
        for (int i = 0; i < 8; i++) {
            float4 v = rv ? *(const float4*)(src + i * 4)
                          : make_float4(0.f, 0.f, 0.f, 0.f);
            v.x *= s; v.y *= s; v.z *= s; v.w *= s;
            aPref[i] = v;
        }
    };

    auto ldB = [&](int c) {
        uint32_t dst = sb + (c & 1) * STG + 2 * TB + bn * 144 + bhf * 64;
        const char* srcH = gBh + c * 128 + bhf * 64;
        const char* srcL = gBl + c * 128 + bhf * 64;
#pragma unroll
        for (int j = 0; j < 4; j++) {
            cpa16(dst + j * 16, srcH + j * 16);
            cpa16(dst + TB + j * 16, srcL + j * 16);
        }
        asm volatile("cp.async.commit_group;" ::: "memory");
    };

    auto stA = [&](int buf) {
        char* dst = smem + buf * STG + arow * 144 + ahalf * 64;
#pragma unroll
        for (int i = 0; i < 8; i++) {
            uint2 vh, vl;
            split_pair(aPref[i].x, aPref[i].y, vh.x, vl.x);
            split_pair(aPref[i].z, aPref[i].w, vh.y, vl.y);
            *(uint2*)(dst + i * 8) = vh;
            *(uint2*)(dst + TB + i * 8) = vl;
        }
    };

    float acc[2][8][4];
#pragma unroll
    for (int i = 0; i < 2; i++)
#pragma unroll
        for (int j = 0; j < 8; j++)
#pragma unroll
            for (int q = 0; q < 4; q++) acc[i][j][q] = 0.f;

    ldA(0);
    ldB(0);

    for (int c = 0; c < 10; c++) {
        const int buf = c & 1;
        stA(buf);
        if (c < 9) {
            ldB(c + 1);
            ldA(c + 1);
            asm volatile("cp.async.wait_group 1;" ::: "memory");
        } else {
            asm volatile("cp.async.wait_group 0;" ::: "memory");
        }
        __syncthreads();

        const char* base = smem + buf * STG;
#pragma unroll
        for (int ks = 0; ks < 4; ks++) {
            uint32_t ah[2][4], al[2][4];
#pragma unroll
            for (int i = 0; i < 2; i++) {
                const char* p = base + (wm * 32 + i * 16 + g) * 144
                              + ks * 32 + tq * 4;
                ah[i][0] = *(const uint32_t*)p;
                ah[i][1] = *(const uint32_t*)(p + 8 * 144);
                ah[i][2] = *(const uint32_t*)(p + 16);
                ah[i][3] = *(const uint32_t*)(p + 8 * 144 + 16);
                al[i][0] = *(const uint32_t*)(p + TB);
                al[i][1] = *(const uint32_t*)(p + TB + 8 * 144);
                al[i][2] = *(const uint32_t*)(p + TB + 16);
                al[i][3] = *(const uint32_t*)(p + TB + 8 * 144 + 16);
            }
            uint32_t bh[8][2], bl[8][2];
#pragma unroll
            for (int j = 0; j < 8; j++) {
                const char* p = base + 2 * TB + (wn * 64 + j * 8 + g) * 144
                              + ks * 32 + tq * 4;
                bh[j][0] = *(const uint32_t*)p;
                bh[j][1] = *(const uint32_t*)(p + 16);
                bl[j][0] = *(const uint32_t*)(p + TB);
                bl[j][1] = *(const uint32_t*)(p + TB + 16);
            }
#pragma unroll
            for (int i = 0; i < 2; i++)
#pragma unroll
                for (int j = 0; j < 8; j++) {
                    MMA16816(acc[i][j], ah[i], bh[j]);
                    MMA16816(acc[i][j], al[i], bh[j]);
                    MMA16816(acc[i][j], ah[i], bl[j]);
                }
        }
        __syncthreads();
    }

    // Epilogue: bias + ReLU, direct stores (float2 per fragment row).
#pragma unroll
    for (int i = 0; i < 2; i++) {
        int r0 = m0 + wm * 32 + i * 16 + g;
        int r1 = r0 + 8;
#pragma unroll
        for (int j = 0; j < 8; j++) {
            int col = wn * 64 + j * 8 + 2 * tq;
            float2 bb = *(float2*)&sbias[col];
            if (r0 < NN) {
                float2 o;
                o.x = fmaxf(acc[i][j][0] + bb.x, 0.f);
                o.y = fmaxf(acc[i][j][1] + bb.y, 0.f);
                *(float2*)(op + (size_t)r0 * 128 + col) = o;
            }
            if (r1 < NN) {
                float2 o;
                o.x = fmaxf(acc[i][j][2] + bb.x, 0.f);
                o.y = fmaxf(acc[i][j][3] + bb.y, 0.f);
                *(float2*)(op + (size_t)r1 * 128 + col) = o;
            }
        }
    }
}

// ---------------------------------------------------------------------------
extern "C" void kernel_launch(void* const* d_in, const int* in_sizes, int n_in,
                              void* d_out, int out_size) {
    const float* x      = (const float*)d_in[0];   // [N, F]
    const void*  ei     = d_in[1];                 // [2, E] int64 or int32
    const void*  et     = d_in[2];                 // [E]    int64 or int32
    const float* W      = (const float*)d_in[3];   // [L, R, F, F]
    const float* roots  = (const float*)d_in[4];   // [L, F, F]
    const float* biases = (const float*)d_in[5];   // [L, F]
    float* out = (float*)d_out;                    // [N, F]

    cudaFuncSetAttribute(gemm_mma_kernel,
                         cudaFuncAttributeMaxDynamicSharedMemorySize, SM_TOTAL);

    detect_kernel<<<1, 32>>>(ei);
    zero_cnt_kernel<<<(NN * RR + 255) / 256, 256>>>();
    count_kernel<<<2048, 256>>>(ei, et);
    inv_kernel<<<(NN * RR + 255) / 256, 256>>>();
    prep_b_kernel<<<(2 * 128 * 640 + 255) / 256, 256>>>(W, roots);

    const int gemm_blocks = (NN + 127) / 128;      // 782
    for (int l = 0; l < 2; l++) {
        zero_S_kernel<<<8192, 256>>>();
        scatter_kernel<<<4096, 256>>>(x, l, ei, et);
        gemm_mma_kernel<<<gemm_blocks, 256, SM_TOTAL>>>(
            x, l, l, biases + (size_t)l * FD, out, (l == 0) ? 1 : 0);
    }
}